// round 1
// baseline (speedup 1.0000x reference)
#include <cuda_runtime.h>
#include <math.h>

#define BB 4
#define TT 2048
#define DM 512
#define HH 8
#define DH 64
#define MROWS (BB*TT)   // 8192

// ---------------- scratch (allocation-free: __device__ globals) ----------------
__device__ float g_q[MROWS * DM];
__device__ float g_k[MROWS * DM];
__device__ float g_v[MROWS * DM];
__device__ float g_ctx[MROWS * DM];
// Fallback attn buffer in case d_out only holds `out` (537 MB, bss zero-init at load)
__device__ float g_attn_fb[(size_t)BB * HH * TT * TT];

// ---------------- GEMM: Y = X @ W^T + b  (M=8192, N=512, K=512) ----------------
// mode 0: write to headed layout (b,h,t,d)  [for q/k/v projections]
// mode 1: write row-major (m, n)            [for final out]
__global__ __launch_bounds__(256) void gemm_xwT_kernel(
    const float* __restrict__ X, const float* __restrict__ W,
    const float* __restrict__ bias, float* __restrict__ Y, int mode)
{
    __shared__ float As[16][68];   // [k][m], padded
    __shared__ float Bs[16][68];   // [k][n], padded
    const int m0 = blockIdx.y * 64;
    const int n0 = blockIdx.x * 64;
    const int tid = threadIdx.x;
    const int tx = tid & 15, ty = tid >> 4;
    const int lr = tid >> 2;          // 0..63
    const int lk = (tid & 3) * 4;     // 0,4,8,12

    float acc[4][4] = {};
    for (int kt = 0; kt < DM; kt += 16) {
        float4 a4 = *(const float4*)&X[(size_t)(m0 + lr) * DM + kt + lk];
        float4 b4 = *(const float4*)&W[(size_t)(n0 + lr) * DM + kt + lk];
        As[lk + 0][lr] = a4.x; As[lk + 1][lr] = a4.y; As[lk + 2][lr] = a4.z; As[lk + 3][lr] = a4.w;
        Bs[lk + 0][lr] = b4.x; Bs[lk + 1][lr] = b4.y; Bs[lk + 2][lr] = b4.z; Bs[lk + 3][lr] = b4.w;
        __syncthreads();
        #pragma unroll
        for (int k = 0; k < 16; k++) {
            float4 av = *(const float4*)&As[k][ty * 4];
            float4 bv = *(const float4*)&Bs[k][tx * 4];
            float a[4] = {av.x, av.y, av.z, av.w};
            float b[4] = {bv.x, bv.y, bv.z, bv.w};
            #pragma unroll
            for (int i = 0; i < 4; i++)
                #pragma unroll
                for (int j = 0; j < 4; j++)
                    acc[i][j] += a[i] * b[j];
        }
        __syncthreads();
    }
    #pragma unroll
    for (int i = 0; i < 4; i++) {
        int m = m0 + ty * 4 + i;
        #pragma unroll
        for (int j = 0; j < 4; j++) {
            int n = n0 + tx * 4 + j;
            float v = acc[i][j] + bias[n];
            if (mode == 0) {
                int b_ = m / TT, t = m % TT, h = n / DH, d = n % DH;
                Y[(((size_t)(b_ * HH + h) * TT) + t) * DH + d] = v;
            } else {
                Y[(size_t)m * DM + n] = v;
            }
        }
    }
}

// ---------------- scores: S[bh] = (q @ k^T) * 1/sqrt(64), raw into attn ----------------
__global__ __launch_bounds__(256) void scores_kernel(
    const float* __restrict__ q, const float* __restrict__ k,
    float* __restrict__ attn)
{
    __shared__ float Qs[64][68];   // [d][m]
    __shared__ float Ks[64][68];   // [d][n]
    const int bh = blockIdx.z;
    const int m0 = blockIdx.y * 64;
    const int n0 = blockIdx.x * 64;
    const float* qb = q + (size_t)bh * TT * DH;
    const float* kb = k + (size_t)bh * TT * DH;
    const int tid = threadIdx.x;
    const int tx = tid & 15, ty = tid >> 4;
    const int lr = tid >> 2;          // 0..63
    const int ld0 = (tid & 3) * 4;    // 0,4,8,12

    #pragma unroll
    for (int c = 0; c < 4; c++) {
        int d = ld0 + c * 16;
        float4 a4 = *(const float4*)&qb[(size_t)(m0 + lr) * DH + d];
        float4 b4 = *(const float4*)&kb[(size_t)(n0 + lr) * DH + d];
        Qs[d + 0][lr] = a4.x; Qs[d + 1][lr] = a4.y; Qs[d + 2][lr] = a4.z; Qs[d + 3][lr] = a4.w;
        Ks[d + 0][lr] = b4.x; Ks[d + 1][lr] = b4.y; Ks[d + 2][lr] = b4.z; Ks[d + 3][lr] = b4.w;
    }
    __syncthreads();

    float acc[4][4] = {};
    #pragma unroll 16
    for (int d = 0; d < 64; d++) {
        float4 av = *(const float4*)&Qs[d][ty * 4];
        float4 bv = *(const float4*)&Ks[d][tx * 4];
        float a[4] = {av.x, av.y, av.z, av.w};
        float b[4] = {bv.x, bv.y, bv.z, bv.w};
        #pragma unroll
        for (int i = 0; i < 4; i++)
            #pragma unroll
            for (int j = 0; j < 4; j++)
                acc[i][j] += a[i] * b[j];
    }

    const float scale = 0.125f;  // 1/sqrt(64)
    float* ab = attn + (size_t)bh * TT * TT;
    #pragma unroll
    for (int i = 0; i < 4; i++) {
        int m = m0 + ty * 4 + i;
        float4 o;
        o.x = acc[i][0] * scale; o.y = acc[i][1] * scale;
        o.z = acc[i][2] * scale; o.w = acc[i][3] * scale;
        *(float4*)&ab[(size_t)m * TT + n0 + tx * 4] = o;
    }
}

// ---------------- softmax in place over rows of 2048 ----------------
__global__ __launch_bounds__(256) void softmax_kernel(float* __restrict__ attn)
{
    const size_t row = blockIdx.x;
    float* p = attn + row * TT;
    const int tid = threadIdx.x;
    __shared__ float smax[8];
    __shared__ float ssum[8];

    float v[8];
    #pragma unroll
    for (int i = 0; i < 8; i++) v[i] = p[tid + i * 256];

    float mx = v[0];
    #pragma unroll
    for (int i = 1; i < 8; i++) mx = fmaxf(mx, v[i]);
    #pragma unroll
    for (int o = 16; o > 0; o >>= 1) mx = fmaxf(mx, __shfl_xor_sync(0xffffffffu, mx, o));
    if ((tid & 31) == 0) smax[tid >> 5] = mx;
    __syncthreads();
    float rmx = smax[0];
    #pragma unroll
    for (int i = 1; i < 8; i++) rmx = fmaxf(rmx, smax[i]);

    float s = 0.f;
    #pragma unroll
    for (int i = 0; i < 8; i++) { v[i] = __expf(v[i] - rmx); s += v[i]; }
    #pragma unroll
    for (int o = 16; o > 0; o >>= 1) s += __shfl_xor_sync(0xffffffffu, s, o);
    if ((tid & 31) == 0) ssum[tid >> 5] = s;
    __syncthreads();
    float rs = 0.f;
    #pragma unroll
    for (int i = 0; i < 8; i++) rs += ssum[i];

    float inv = 1.f / rs;
    #pragma unroll
    for (int i = 0; i < 8; i++) p[tid + i * 256] = v[i] * inv;
}

// ---------------- ctx: C[bh] = attn[bh] @ v[bh], write (b,t, h*64+d) ----------------
__global__ __launch_bounds__(256) void ctx_kernel(
    const float* __restrict__ attn, const float* __restrict__ v,
    float* __restrict__ ctx)
{
    __shared__ float Ps[32][68];   // [k][m], padded
    __shared__ float Vs[32][64];   // [k][d]
    const int bh = blockIdx.y;
    const int b_ = bh >> 3, h = bh & 7;
    const int m0 = blockIdx.x * 64;
    const float* P = attn + (size_t)bh * TT * TT;
    const float* vb = v + (size_t)bh * TT * DH;
    const int tid = threadIdx.x;
    const int tx = tid & 15, ty = tid >> 4;
    const int pr = tid >> 2;          // 0..63
    const int pk0 = (tid & 3) * 8;    // 0,8,16,24
    const int vr = tid >> 3;          // 0..31
    const int vd = (tid & 7) * 8;     // 0..56

    float acc[4][4] = {};
    for (int kt = 0; kt < TT; kt += 32) {
        float4 pa = *(const float4*)&P[(size_t)(m0 + pr) * TT + kt + pk0];
        float4 pb = *(const float4*)&P[(size_t)(m0 + pr) * TT + kt + pk0 + 4];
        Ps[pk0 + 0][pr] = pa.x; Ps[pk0 + 1][pr] = pa.y; Ps[pk0 + 2][pr] = pa.z; Ps[pk0 + 3][pr] = pa.w;
        Ps[pk0 + 4][pr] = pb.x; Ps[pk0 + 5][pr] = pb.y; Ps[pk0 + 6][pr] = pb.z; Ps[pk0 + 7][pr] = pb.w;
        *(float4*)&Vs[vr][vd]     = *(const float4*)&vb[(size_t)(kt + vr) * DH + vd];
        *(float4*)&Vs[vr][vd + 4] = *(const float4*)&vb[(size_t)(kt + vr) * DH + vd + 4];
        __syncthreads();
        #pragma unroll
        for (int kk = 0; kk < 32; kk++) {
            float4 av = *(const float4*)&Ps[kk][ty * 4];
            float4 bv = *(const float4*)&Vs[kk][tx * 4];
            float a[4] = {av.x, av.y, av.z, av.w};
            float b[4] = {bv.x, bv.y, bv.z, bv.w};
            #pragma unroll
            for (int i = 0; i < 4; i++)
                #pragma unroll
                for (int j = 0; j < 4; j++)
                    acc[i][j] += a[i] * b[j];
        }
        __syncthreads();
    }
    #pragma unroll
    for (int i = 0; i < 4; i++) {
        int t = m0 + ty * 4 + i;
        #pragma unroll
        for (int j = 0; j < 4; j++) {
            int d = tx * 4 + j;
            ctx[((size_t)(b_ * TT + t)) * DM + h * DH + d] = acc[i][j];
        }
    }
}

// ---------------- launch ----------------
extern "C" void kernel_launch(void* const* d_in, const int* in_sizes, int n_in,
                              void* d_out, int out_size)
{
    const float* Q  = (const float*)d_in[0];
    const float* K  = (const float*)d_in[1];
    const float* V  = (const float*)d_in[2];
    const float* Wq = (const float*)d_in[3];
    const float* bq = (const float*)d_in[4];
    const float* Wk = (const float*)d_in[5];
    const float* bk = (const float*)d_in[6];
    const float* Wv = (const float*)d_in[7];
    const float* bv = (const float*)d_in[8];
    const float* Wo = (const float*)d_in[9];
    const float* bo = (const float*)d_in[10];

    float* out = (float*)d_out;
    const long long OUT_ELEMS  = (long long)BB * TT * DM;                 // 4,194,304
    const long long ATTN_ELEMS = (long long)BB * HH * TT * TT;            // 134,217,728

    float *q, *k, *v, *ctx, *attn;
    { void* p; cudaGetSymbolAddress(&p, g_q);   q   = (float*)p; }
    { void* p; cudaGetSymbolAddress(&p, g_k);   k   = (float*)p; }
    { void* p; cudaGetSymbolAddress(&p, g_v);   v   = (float*)p; }
    { void* p; cudaGetSymbolAddress(&p, g_ctx); ctx = (float*)p; }
    if ((long long)out_size >= OUT_ELEMS + ATTN_ELEMS) {
        attn = out + OUT_ELEMS;
    } else {
        void* p; cudaGetSymbolAddress(&p, g_attn_fb); attn = (float*)p;
    }

    dim3 gg(DM / 64, MROWS / 64);            // (8, 128)
    gemm_xwT_kernel<<<gg, 256>>>(Q, Wq, bq, q, 0);
    gemm_xwT_kernel<<<gg, 256>>>(K, Wk, bk, k, 0);
    gemm_xwT_kernel<<<gg, 256>>>(V, Wv, bv, v, 0);

    dim3 gs(TT / 64, TT / 64, BB * HH);      // (32, 32, 32)
    scores_kernel<<<gs, 256>>>(q, k, attn);

    softmax_kernel<<<(unsigned)(BB * HH * TT), 256>>>(attn);

    dim3 gc(TT / 64, BB * HH);               // (32, 32)
    ctx_kernel<<<gc, 256>>>(attn, v, ctx);

    gemm_xwT_kernel<<<gg, 256>>>(ctx, Wo, bo, out, 1);
}